// round 1
// baseline (speedup 1.0000x reference)
#include <cuda_runtime.h>
#include <cuda_bf16.h>
#include <math.h>

// Problem constants
#define BATCH 64
#define SEQ 64
#define EMBED 1024
#define HEADS 16
#define HDIM 64
#define VOCAB 50257
#define ROWS (BATCH * SEQ)          // 4096
#define QKV_ELEMS ((size_t)ROWS * EMBED)

// ---------------- scratch (device globals; no allocation allowed) ----------------
__device__ float g_emb[QKV_ELEMS];
__device__ float g_Q[QKV_ELEMS];
__device__ float g_K[QKV_ELEMS];
__device__ float g_V[QKV_ELEMS];
__device__ float g_cat[QKV_ELEMS];
__device__ float g_y[QKV_ELEMS];

// ---------------- K1: embedding gather + positional add ----------------
__global__ void embed_kernel(const int* __restrict__ x,
                             const float* __restrict__ E,
                             const float* __restrict__ pe) {
    int row = blockIdx.x;            // b*SEQ + s
    int s = row & (SEQ - 1);
    int tok = x[row];
    const float4* e4 = (const float4*)(E + (size_t)tok * EMBED);
    const float4* p4 = (const float4*)(pe + (size_t)s * EMBED);
    float4* o4 = (float4*)(g_emb + (size_t)row * EMBED);
    int i = threadIdx.x;             // 256 threads, 256 float4 per row
    float4 a = e4[i], b = p4[i];
    o4[i] = make_float4(a.x + b.x, a.y + b.y, a.z + b.z, a.w + b.w);
}

// ---------------- K2: per-head QKV projection ----------------
// block = (b, h, which). Computes 64x64 tile: Out[s][e] = sum_d emb[b,s,d] * W[h][d][e] + bias[h][e]
__global__ __launch_bounds__(256) void qkv_kernel(
    const float* __restrict__ Wq, const float* __restrict__ bq,
    const float* __restrict__ Wk, const float* __restrict__ bk,
    const float* __restrict__ Wv, const float* __restrict__ bv) {
    int b = blockIdx.x, h = blockIdx.y, w = blockIdx.z;
    const float* W = (w == 0 ? Wq : (w == 1 ? Wk : Wv)) + (size_t)h * EMBED * HDIM;
    const float* bias = (w == 0 ? bq : (w == 1 ? bk : bv)) + h * HDIM;
    float* Out = (w == 0 ? g_Q : (w == 1 ? g_K : g_V)) + (size_t)(b * HEADS + h) * SEQ * HDIM;
    const float* Ab = g_emb + (size_t)b * SEQ * EMBED;

    __shared__ float As[64][17];
    __shared__ float Bs[16][64];

    int tid = threadIdx.x;
    int tx = tid & 15, ty = tid >> 4;
    int s0 = ty * 4, e0 = tx * 4;
    float acc[4][4] = {};

    int lm = tid >> 2, lk = (tid & 3) * 4;        // A-tile load: row lm, 4 floats at lk
    int bkr = tid >> 4, be = (tid & 15) * 4;      // B-tile load

    for (int kt = 0; kt < EMBED; kt += 16) {
        float4 av = *(const float4*)(Ab + (size_t)lm * EMBED + kt + lk);
        As[lm][lk] = av.x; As[lm][lk + 1] = av.y; As[lm][lk + 2] = av.z; As[lm][lk + 3] = av.w;
        float4 bv4 = *(const float4*)(W + (size_t)(kt + bkr) * HDIM + be);
        *(float4*)&Bs[bkr][be] = bv4;
        __syncthreads();
#pragma unroll
        for (int kk = 0; kk < 16; kk++) {
            float a0 = As[s0][kk], a1 = As[s0 + 1][kk], a2 = As[s0 + 2][kk], a3 = As[s0 + 3][kk];
            float4 bb = *(float4*)&Bs[kk][e0];
            acc[0][0] += a0 * bb.x; acc[0][1] += a0 * bb.y; acc[0][2] += a0 * bb.z; acc[0][3] += a0 * bb.w;
            acc[1][0] += a1 * bb.x; acc[1][1] += a1 * bb.y; acc[1][2] += a1 * bb.z; acc[1][3] += a1 * bb.w;
            acc[2][0] += a2 * bb.x; acc[2][1] += a2 * bb.y; acc[2][2] += a2 * bb.z; acc[2][3] += a2 * bb.w;
            acc[3][0] += a3 * bb.x; acc[3][1] += a3 * bb.y; acc[3][2] += a3 * bb.z; acc[3][3] += a3 * bb.w;
        }
        __syncthreads();
    }
#pragma unroll
    for (int i = 0; i < 4; i++)
#pragma unroll
        for (int j = 0; j < 4; j++)
            Out[(size_t)(s0 + i) * HDIM + e0 + j] = acc[i][j] + bias[e0 + j];
}

// ---------------- K3: causal attention per (b, h) ----------------
__global__ __launch_bounds__(256) void attn_kernel() {
    int b = blockIdx.x, h = blockIdx.y;
    const float* Qb = g_Q + (size_t)(b * HEADS + h) * SEQ * HDIM;
    const float* Kb = g_K + (size_t)(b * HEADS + h) * SEQ * HDIM;
    const float* Vb = g_V + (size_t)(b * HEADS + h) * SEQ * HDIM;

    __shared__ float sKV[64][65];
    __shared__ float sS[64][68];

    int tid = threadIdx.x;
    // load K
    for (int idx = tid; idx < 64 * 64; idx += 256) {
        int r = idx >> 6, c = idx & 63;
        sKV[r][c] = Kb[idx];
    }
    __syncthreads();

    // phase 1: scores[i][j] = Q[i] . K[j]
    int i = tid >> 2;
    int jb = (tid & 3) * 16;
    {
        float accS[16] = {};
        const float4* Q4 = (const float4*)(Qb + (size_t)i * HDIM);
#pragma unroll
        for (int ec = 0; ec < 16; ec++) {
            float4 q = Q4[ec];
#pragma unroll
            for (int jj = 0; jj < 16; jj++) {
                const float* kr = &sKV[jb + jj][ec * 4];
                accS[jj] += q.x * kr[0] + q.y * kr[1] + q.z * kr[2] + q.w * kr[3];
            }
        }
#pragma unroll
        for (int jj = 0; jj < 16; jj++) sS[i][jb + jj] = accS[jj];
    }
    __syncthreads();

    // phase 2: causal softmax, one row per thread (threads 0..63)
    if (tid < 64) {
        int r = tid;
        const float scale = 0.125f; // 1/sqrt(64)
        float mx = -1e30f;
        for (int j = 0; j <= r; j++) {
            float v = sS[r][j] * scale;
            sS[r][j] = v;
            mx = fmaxf(mx, v);
        }
        float sum = 0.f;
        for (int j = 0; j <= r; j++) {
            float e = expf(sS[r][j] - mx);
            sS[r][j] = e;
            sum += e;
        }
        float inv = 1.f / sum;
        for (int j = 0; j <= r; j++) sS[r][j] *= inv;
        for (int j = r + 1; j < 64; j++) sS[r][j] = 0.f;
    }
    __syncthreads();

    // load V (reuse sKV)
    for (int idx = tid; idx < 64 * 64; idx += 256) {
        int r = idx >> 6, c = idx & 63;
        sKV[r][c] = Vb[idx];
    }
    __syncthreads();

    // phase 3: out[i][e] = sum_j w[i][j] * V[j][e]
    int eb = (tid & 3) * 16;
    float accO[16] = {};
    for (int j = 0; j < 64; j++) {
        float w = sS[i][j];
        const float* vr = &sKV[j][eb];
#pragma unroll
        for (int ee = 0; ee < 16; ee++) accO[ee] += w * vr[ee];
    }
    float* dst = g_cat + (size_t)(b * SEQ + i) * EMBED + h * HDIM + eb;
#pragma unroll
    for (int ee = 0; ee < 16; ee++) dst[ee] = accO[ee];
}

// ---------------- K4/K5: generic 128x128-tile SGEMM, 8x8 per thread, double-buffered ----------------
// C[m][n] = sum_k A[m][k]*B[k][n] + bias[n] (+ resid[m][n] if ADD_RESID)
// A row-major [M,K]; B row-major [K,N]; M multiple of 128; N arbitrary (guarded).
template <bool ADD_RESID>
__global__ __launch_bounds__(256) void sgemm128(
    const float* __restrict__ A, const float* __restrict__ B,
    const float* __restrict__ bias, const float* __restrict__ resid,
    float* __restrict__ C, int N, int K) {
    __shared__ float As[2][8][128];
    __shared__ float Bs[2][8][128];

    const int tid = threadIdx.x;
    const int bm = blockIdx.x, bn = blockIdx.y;

    // global-load mapping
    const int am = tid >> 1;                 // 0..127
    const int ak = (tid & 1) << 2;           // 0 or 4
    const int bkr = tid >> 5;                // 0..7
    const int bn4 = (tid & 31) << 2;         // 0..124
    const size_t arow = (size_t)(bm * 128 + am) * K;
    const size_t ncol = (size_t)bn * 128 + bn4;

    // compute mapping
    const int tx = tid & 15, ty = tid >> 4;
    const int m0 = ty * 8, n0 = tx * 8;

    float acc[8][8] = {};
    float4 aReg;
    float bReg[4];

    // prologue: tile 0
    aReg = *(const float4*)(A + arow + ak);
#pragma unroll
    for (int i2 = 0; i2 < 4; i2++)
        bReg[i2] = (ncol + i2 < (size_t)N) ? B[(size_t)bkr * N + ncol + i2] : 0.f;

    As[0][ak + 0][am] = aReg.x; As[0][ak + 1][am] = aReg.y;
    As[0][ak + 2][am] = aReg.z; As[0][ak + 3][am] = aReg.w;
    *(float4*)&Bs[0][bkr][bn4] = make_float4(bReg[0], bReg[1], bReg[2], bReg[3]);
    __syncthreads();

    const int nt = K >> 3;
    for (int kt = 0; kt < nt; kt++) {
        const int cur = kt & 1;
        if (kt + 1 < nt) {
            aReg = *(const float4*)(A + arow + (size_t)(kt + 1) * 8 + ak);
            const size_t gk = (size_t)(kt + 1) * 8 + bkr;
#pragma unroll
            for (int i2 = 0; i2 < 4; i2++)
                bReg[i2] = (ncol + i2 < (size_t)N) ? B[gk * N + ncol + i2] : 0.f;
        }
#pragma unroll
        for (int k = 0; k < 8; k++) {
            float a[8], bb[8];
            *(float4*)(a)     = *(float4*)&As[cur][k][m0];
            *(float4*)(a + 4) = *(float4*)&As[cur][k][m0 + 4];
            *(float4*)(bb)     = *(float4*)&Bs[cur][k][n0];
            *(float4*)(bb + 4) = *(float4*)&Bs[cur][k][n0 + 4];
#pragma unroll
            for (int i2 = 0; i2 < 8; i2++)
#pragma unroll
                for (int j2 = 0; j2 < 8; j2++)
                    acc[i2][j2] += a[i2] * bb[j2];
        }
        if (kt + 1 < nt) {
            const int nx = cur ^ 1;
            As[nx][ak + 0][am] = aReg.x; As[nx][ak + 1][am] = aReg.y;
            As[nx][ak + 2][am] = aReg.z; As[nx][ak + 3][am] = aReg.w;
            *(float4*)&Bs[nx][bkr][bn4] = make_float4(bReg[0], bReg[1], bReg[2], bReg[3]);
        }
        __syncthreads();
    }

    // epilogue
#pragma unroll
    for (int i2 = 0; i2 < 8; i2++) {
        const size_t m = (size_t)bm * 128 + m0 + i2;
#pragma unroll
        for (int j2 = 0; j2 < 8; j2++) {
            const size_t n = (size_t)bn * 128 + n0 + j2;
            if (n < (size_t)N) {
                float v = acc[i2][j2] + bias[n];
                if (ADD_RESID) v += resid[m * N + n];
                C[m * N + n] = v;
            }
        }
    }
}

// ---------------- launch ----------------
extern "C" void kernel_launch(void* const* d_in, const int* in_sizes, int n_in,
                              void* d_out, int out_size) {
    const int*   x  = (const int*)d_in[0];
    const float* E  = (const float*)d_in[1];
    const float* pe = (const float*)d_in[2];
    const float* Wq = (const float*)d_in[3];
    const float* bq = (const float*)d_in[4];
    const float* Wk = (const float*)d_in[5];
    const float* bk = (const float*)d_in[6];
    const float* Wv = (const float*)d_in[7];
    const float* bv = (const float*)d_in[8];
    const float* Wo = (const float*)d_in[9];
    const float* bo = (const float*)d_in[10];
    const float* Wu = (const float*)d_in[11];
    const float* bu = (const float*)d_in[12];
    float* out = (float*)d_out;

    float *emb, *catp, *yp;
    cudaGetSymbolAddress((void**)&emb, g_emb);
    cudaGetSymbolAddress((void**)&catp, g_cat);
    cudaGetSymbolAddress((void**)&yp, g_y);

    // K1: embedding
    embed_kernel<<<ROWS, 256>>>(x, E, pe);

    // K2: QKV projections
    qkv_kernel<<<dim3(BATCH, HEADS, 3), 256>>>(Wq, bq, Wk, bk, Wv, bv);

    // K3: attention
    attn_kernel<<<dim3(BATCH, HEADS), 256>>>();

    // K4: output projection + bias + residual -> g_y
    sgemm128<true><<<dim3(ROWS / 128, EMBED / 128), 256>>>(catp, Wo, bo, emb, yp, EMBED, EMBED);

    // K5: unembedding -> logits
    const int nTilesV = (VOCAB + 127) / 128;   // 393
    sgemm128<false><<<dim3(ROWS / 128, nTilesV), 256>>>(yp, Wu, bu, nullptr, out, VOCAB, EMBED);
}

// round 4
// speedup vs baseline: 2.4928x; 2.4928x over previous
#include <cuda_runtime.h>
#include <cuda_bf16.h>
#include <math.h>
#include <stdint.h>

// Problem constants
#define BATCH 64
#define SEQ 64
#define EMBED 1024
#define HEADS 16
#define HDIM 64
#define VOCAB 50257
#define VPAD 50304                    // padded to multiple of 128
#define ROWS (BATCH * SEQ)            // 4096

// ---------------- scratch (device globals; no allocation allowed) ----------------
__device__ __align__(128) float    g_emb[(size_t)ROWS * EMBED];        // fp32 residual
__device__ __align__(128) float    g_QKV[(size_t)ROWS * 3 * EMBED];    // fp32 QKV
__device__ __align__(128) uint32_t g_embA[2][(size_t)ROWS * EMBED / 2];  // bf16x2 hi/lo
__device__ __align__(128) uint32_t g_catA[2][(size_t)ROWS * EMBED / 2];
__device__ __align__(128) uint32_t g_yA[2][(size_t)ROWS * EMBED / 2];
__device__ __align__(128) uint32_t g_W3A[2][(size_t)EMBED * 3 * EMBED / 2];
__device__ __align__(128) uint32_t g_WoA[2][(size_t)EMBED * EMBED / 2];
__device__ __align__(128) uint32_t g_WuA[2][(size_t)EMBED * VPAD / 2];
__device__ __align__(128) float    g_b3[3 * EMBED];

// ============================================================================
// helpers
// ============================================================================
__device__ __forceinline__ uint32_t smem_u32(const void* p) {
    uint32_t a;
    asm("{ .reg .u64 t; cvta.to.shared.u64 t, %1; cvt.u32.u64 %0, t; }" : "=r"(a) : "l"(p));
    return a;
}
// pack (v0 -> low half, v1 -> high half)
__device__ __forceinline__ uint32_t cvt_bf16x2(float lo, float hi) {
    uint32_t r;
    asm("cvt.rn.bf16x2.f32 %0, %1, %2;" : "=r"(r) : "f"(hi), "f"(lo));
    return r;
}
__device__ __forceinline__ void split2(float v0, float v1, uint32_t& hi, uint32_t& lo) {
    hi = cvt_bf16x2(v0, v1);
    float r0 = v0 - __uint_as_float(hi << 16);
    float r1 = v1 - __uint_as_float(hi & 0xFFFF0000u);
    lo = cvt_bf16x2(r0, r1);
}
__device__ __forceinline__ void cp16(uint32_t dst, const void* src) {
    asm volatile("cp.async.cg.shared.global [%0], [%1], 16;" :: "r"(dst), "l"(src));
}
__device__ __forceinline__ void ldsm_x4(uint32_t* r, uint32_t addr) {
    asm volatile("ldmatrix.sync.aligned.m8n8.x4.shared.b16 {%0,%1,%2,%3}, [%4];"
                 : "=r"(r[0]), "=r"(r[1]), "=r"(r[2]), "=r"(r[3]) : "r"(addr));
}
__device__ __forceinline__ void ldsm_x4_t(uint32_t* r, uint32_t addr) {
    asm volatile("ldmatrix.sync.aligned.m8n8.x4.trans.shared.b16 {%0,%1,%2,%3}, [%4];"
                 : "=r"(r[0]), "=r"(r[1]), "=r"(r[2]), "=r"(r[3]) : "r"(addr));
}
__device__ __forceinline__ void mma16816(float* c, const uint32_t* a, const uint32_t* b) {
    asm volatile(
        "mma.sync.aligned.m16n8k16.row.col.f32.bf16.bf16.f32 "
        "{%0,%1,%2,%3}, {%4,%5,%6,%7}, {%8,%9}, {%0,%1,%2,%3};"
        : "+f"(c[0]), "+f"(c[1]), "+f"(c[2]), "+f"(c[3])
        : "r"(a[0]), "r"(a[1]), "r"(a[2]), "r"(a[3]), "r"(b[0]), "r"(b[1]));
}

// ---------------- K1: embedding gather + pe; write fp32 + bf16 hi/lo ----------------
__global__ void embed_kernel(const int* __restrict__ x,
                             const float* __restrict__ E,
                             const float* __restrict__ pe) {
    int row = blockIdx.x;
    int s = row & (SEQ - 1);
    int tok = x[row];
    int i = threadIdx.x;                 // 256 threads * 4 floats
    float4 a = ((const float4*)(E + (size_t)tok * EMBED))[i];
    float4 p = ((const float4*)(pe + (size_t)s * EMBED))[i];
    float4 v = make_float4(a.x + p.x, a.y + p.y, a.z + p.z, a.w + p.w);
    ((float4*)(g_emb + (size_t)row * EMBED))[i] = v;
    uint32_t h0, l0, h1, l1;
    split2(v.x, v.y, h0, l0);
    split2(v.z, v.w, h1, l1);
    size_t idx = (size_t)row * 512 + (size_t)i * 2;
    g_embA[0][idx] = h0; g_embA[0][idx + 1] = h1;
    g_embA[1][idx] = l0; g_embA[1][idx + 1] = l1;
}

// ---------------- conv kernels: repack + bf16 split weights ----------------
__global__ void convW3(const float* __restrict__ Wq, const float* __restrict__ bq,
                       const float* __restrict__ Wk, const float* __restrict__ bk,
                       const float* __restrict__ Wv, const float* __restrict__ bv) {
    int idx = blockIdx.x * 256 + threadIdx.x;       // over 1024*1536 pairs
    if (idx < EMBED * 1536) {
        int d = idx / 1536, p = idx % 1536;
        int col = p * 2;
        int w = col >> 10, rem = col & 1023;
        int h = rem >> 6, e = rem & 63;
        const float* W = (w == 0 ? Wq : (w == 1 ? Wk : Wv));
        size_t sidx = ((size_t)h * EMBED + d) * 64 + e;
        uint32_t hi, lo;
        split2(W[sidx], W[sidx + 1], hi, lo);
        g_W3A[0][(size_t)d * 1536 + p] = hi;
        g_W3A[1][(size_t)d * 1536 + p] = lo;
    }
    if (idx < 3 * EMBED) {
        int w = idx >> 10, rem = idx & 1023;
        const float* B = (w == 0 ? bq : (w == 1 ? bk : bv));
        g_b3[idx] = B[rem];
    }
}

__global__ void convWo(const float* __restrict__ Wo) {
    int idx = blockIdx.x * 256 + threadIdx.x;       // over 1024*512 pairs
    if (idx >= EMBED * 512) return;
    int rp = idx;                                    // row*512 + p
    size_t s = (size_t)rp * 2;
    uint32_t hi, lo;
    split2(Wo[s], Wo[s + 1], hi, lo);
    g_WoA[0][rp] = hi;
    g_WoA[1][rp] = lo;
}

__global__ void convWu(const float* __restrict__ Wu) {
    int idx = blockIdx.x * 256 + threadIdx.x;       // over 1024*(VPAD/2)
    if (idx >= EMBED * (VPAD / 2)) return;
    int k = idx / (VPAD / 2), p = idx % (VPAD / 2);
    int n = p * 2;
    float v0 = (n < VOCAB) ? Wu[(size_t)k * VOCAB + n] : 0.f;
    float v1 = (n + 1 < VOCAB) ? Wu[(size_t)k * VOCAB + n + 1] : 0.f;
    uint32_t hi, lo;
    split2(v0, v1, hi, lo);
    g_WuA[0][(size_t)k * (VPAD / 2) + p] = hi;
    g_WuA[1][(size_t)k * (VPAD / 2) + p] = lo;
}

// ---------------- K3: causal attention per (b, h) ----------------
__global__ __launch_bounds__(256) void attn_kernel() {
    int b = blockIdx.x, h = blockIdx.y;
    const float* base = g_QKV + (size_t)b * SEQ * 3072;

    __shared__ float sKV[64][65];
    __shared__ float sS[64][68];

    int tid = threadIdx.x;
    for (int idx = tid; idx < 64 * 64; idx += 256) {
        int r = idx >> 6, c = idx & 63;
        sKV[r][c] = base[(size_t)r * 3072 + 1024 + h * 64 + c];
    }
    __syncthreads();

    int i = tid >> 2;
    int jb = (tid & 3) * 16;
    {
        float accS[16] = {};
        const float4* Q4 = (const float4*)(base + (size_t)i * 3072 + h * 64);
#pragma unroll
        for (int ec = 0; ec < 16; ec++) {
            float4 q = Q4[ec];
#pragma unroll
            for (int jj = 0; jj < 16; jj++) {
                const float* kr = &sKV[jb + jj][ec * 4];
                accS[jj] += q.x * kr[0] + q.y * kr[1] + q.z * kr[2] + q.w * kr[3];
            }
        }
#pragma unroll
        for (int jj = 0; jj < 16; jj++) sS[i][jb + jj] = accS[jj];
    }
    __syncthreads();

    if (tid < 64) {
        int r = tid;
        const float scale = 0.125f;
        float mx = -1e30f;
        for (int j = 0; j <= r; j++) {
            float v = sS[r][j] * scale;
            sS[r][j] = v;
            mx = fmaxf(mx, v);
        }
        float sum = 0.f;
        for (int j = 0; j <= r; j++) {
            float e = expf(sS[r][j] - mx);
            sS[r][j] = e;
            sum += e;
        }
        float inv = 1.f / sum;
        for (int j = 0; j <= r; j++) sS[r][j] *= inv;
        for (int j = r + 1; j < 64; j++) sS[r][j] = 0.f;
    }
    __syncthreads();

    for (int idx = tid; idx < 64 * 64; idx += 256) {
        int r = idx >> 6, c = idx & 63;
        sKV[r][c] = base[(size_t)r * 3072 + 2048 + h * 64 + c];
    }
    __syncthreads();

    int eb = (tid & 3) * 16;
    float accO[16] = {};
    for (int j = 0; j < 64; j++) {
        float w = sS[i][j];
        const float* vr = &sKV[j][eb];
#pragma unroll
        for (int ee = 0; ee < 16; ee++) accO[ee] += w * vr[ee];
    }
    // write packed bf16 hi/lo to g_catA
    uint32_t hp[8], lp[8];
#pragma unroll
    for (int p = 0; p < 8; p++) split2(accO[2 * p], accO[2 * p + 1], hp[p], lp[p]);
    size_t o = ((size_t)(b * SEQ + i) * 1024 + h * 64 + eb) >> 1;    // mult of 8
    ((uint4*)&g_catA[0][o])[0] = make_uint4(hp[0], hp[1], hp[2], hp[3]);
    ((uint4*)&g_catA[0][o])[1] = make_uint4(hp[4], hp[5], hp[6], hp[7]);
    ((uint4*)&g_catA[1][o])[0] = make_uint4(lp[0], lp[1], lp[2], lp[3]);
    ((uint4*)&g_catA[1][o])[1] = make_uint4(lp[4], lp[5], lp[6], lp[7]);
}

// ============================================================================
// HMMA GEMM: C[M,N] = A[M,1024] @ B[1024,N], 3x bf16 split, fp32 accum.
// CTA tile 128x128, 8 warps (2m x 4n), warp tile 64x32, mma m16n8k16.
// 5-stage cp.async pipeline. A smem rows padded to 48B; B smem XOR-swizzled.
// MODE 0: out fp32 = C + bias                      (QKV)
// MODE 1: split2(C + bias + resid) -> outHi/outLo  (O-proj -> y bf16 hi/lo)
// MODE 2: out fp32 = C + bias, col < VOCAB guard   (unembed)
// ============================================================================
#define NST 5
#define STG_BYTES 20480
#define OFF_AHI 0
#define OFF_ALO 6144
#define OFF_BHI 12288
#define OFF_BLO 16384
#define GEMM_SMEM (NST * STG_BYTES)     // 102400

template <int MODE>
__global__ __launch_bounds__(256, 1) void hmma_gemm(
    const uint32_t* __restrict__ Ahi, const uint32_t* __restrict__ Alo,
    const uint32_t* __restrict__ Bhi, const uint32_t* __restrict__ Blo,
    const float* __restrict__ bias, const float* __restrict__ resid,
    float* __restrict__ out, uint32_t* __restrict__ outHi, uint32_t* __restrict__ outLo,
    int ldb, int ldc) {
    extern __shared__ char sm[];
    const uint32_t smb = smem_u32(sm);
    const int t = threadIdx.x;
    const int mBase = blockIdx.x * 128;
    const int nBase = blockIdx.y * 128;

    // ---- global load mapping (cp.async, 4x 16B per thread per stage) ----
    const int aRow = t >> 1, aCh = t & 1;          // A: 128 rows x 2 chunks
    const int bRow = t >> 4, bCh = t & 15;         // B: 16 rows x 16 chunks
    const char* aHiP = (const char*)Ahi + (size_t)(mBase + aRow) * 2048 + aCh * 16;
    const char* aLoP = (const char*)Alo + (size_t)(mBase + aRow) * 2048 + aCh * 16;
    const char* bHiP = (const char*)Bhi + ((size_t)bRow * ldb + nBase) * 2 + bCh * 16;
    const char* bLoP = (const char*)Blo + ((size_t)bRow * ldb + nBase) * 2 + bCh * 16;
    const size_t bStep = (size_t)ldb * 32;         // 16 rows * ldb elems * 2B
    const uint32_t aDst = aRow * 48 + aCh * 16;
    const uint32_t bDst = bRow * 256 + ((bCh ^ (bRow & 7)) * 16);

    // ---- compute mapping ----
    const int w = t >> 5, L = t & 31;
    const int wm = w >> 2, wn = w & 3;             // warp tile: (wm*64, wn*32)
    const int mat = L >> 3, r = L & 7;
    const uint32_t aLd = (uint32_t)((wm * 64 + (mat & 1) * 8 + r) * 48 + (mat >> 1) * 16);
    const int kq = (mat & 1) * 8 + r;
    const int qr = L >> 2, qc = (L & 3) * 2;

    float acc[4][4][4] = {};

#define LOAD_TILE(kt) do {                                                   \
        uint32_t _b = smb + ((kt) % NST) * STG_BYTES;                        \
        cp16(_b + OFF_AHI + aDst, aHiP + (size_t)(kt) * 32);                 \
        cp16(_b + OFF_ALO + aDst, aLoP + (size_t)(kt) * 32);                 \
        cp16(_b + OFF_BHI + bDst, bHiP + (size_t)(kt) * bStep);              \
        cp16(_b + OFF_BLO + bDst, bLoP + (size_t)(kt) * bStep);              \
    } while (0)

    int fetch = 0;
    for (; fetch < NST - 1; fetch++) {
        LOAD_TILE(fetch);
        asm volatile("cp.async.commit_group;" ::: "memory");
    }

    for (int kt = 0; kt < 64; kt++) {
        if (fetch < 64) { LOAD_TILE(fetch); fetch++; }
        asm volatile("cp.async.commit_group;" ::: "memory");
        asm volatile("cp.async.wait_group %0;" :: "n"(NST - 1));
        __syncthreads();

        const uint32_t sb = smb + (kt % NST) * STG_BYTES;
        uint32_t a_hi[4][4], a_lo[4][4], b_hi[4][2], b_lo[4][2];
#pragma unroll
        for (int i = 0; i < 4; i++) ldsm_x4(a_hi[i], sb + OFF_AHI + aLd + i * 768);
#pragma unroll
        for (int i = 0; i < 4; i++) ldsm_x4(a_lo[i], sb + OFF_ALO + aLd + i * 768);
#pragma unroll
        for (int j2 = 0; j2 < 2; j2++) {
            int c = wn * 4 + j2 * 2 + (mat >> 1);
            uint32_t ad = (uint32_t)(kq * 256 + ((c ^ (kq & 7)) * 16));
            uint32_t tmp[4];
            ldsm_x4_t(tmp, sb + OFF_BHI + ad);
            b_hi[j2 * 2][0] = tmp[0]; b_hi[j2 * 2][1] = tmp[1];
            b_hi[j2 * 2 + 1][0] = tmp[2]; b_hi[j2 * 2 + 1][1] = tmp[3];
            ldsm_x4_t(tmp, sb + OFF_BLO + ad);
            b_lo[j2 * 2][0] = tmp[0]; b_lo[j2 * 2][1] = tmp[1];
            b_lo[j2 * 2 + 1][0] = tmp[2]; b_lo[j2 * 2 + 1][1] = tmp[3];
        }
#pragma unroll
        for (int i = 0; i < 4; i++)
#pragma unroll
            for (int j = 0; j < 4; j++) {
                mma16816(acc[i][j], a_hi[i], b_hi[j]);
                mma16816(acc[i][j], a_hi[i], b_lo[j]);
                mma16816(acc[i][j], a_lo[i], b_hi[j]);
            }
        __syncthreads();
    }

    // ---- epilogue ----
#pragma unroll
    for (int i = 0; i < 4; i++) {
        const int row0 = mBase + wm * 64 + i * 16 + qr;
#pragma unroll
        for (int j = 0; j < 4; j++) {
            const int col = nBase + wn * 32 + j * 8 + qc;
            float v0 = acc[i][j][0], v1 = acc[i][j][1];
            float v2 = acc[i][j][2], v3 = acc[i][j][3];
            if (MODE == 0) {
                float b0 = bias[col], b1 = bias[col + 1];
                *(float2*)&out[(size_t)row0 * ldc + col] = make_float2(v0 + b0, v1 + b1);
                *(float2*)&out[(size_t)(row0 + 8) * ldc + col] = make_float2(v2 + b0, v3 + b1);
            } else if (MODE == 1) {
                float b0 = bias[col], b1 = bias[col + 1];
                float u0 = v0 + b0 + resid[(size_t)row0 * 1024 + col];
                float u1 = v1 + b1 + resid[(size_t)row0 * 1024 + col + 1];
                uint32_t hi, lo;
                split2(u0, u1, hi, lo);
                outHi[(size_t)row0 * 512 + (col >> 1)] = hi;
                outLo[(size_t)row0 * 512 + (col >> 1)] = lo;
                float u2 = v2 + b0 + resid[(size_t)(row0 + 8) * 1024 + col];
                float u3 = v3 + b1 + resid[(size_t)(row0 + 8) * 1024 + col + 1];
                split2(u2, u3, hi, lo);
                outHi[(size_t)(row0 + 8) * 512 + (col >> 1)] = hi;
                outLo[(size_t)(row0 + 8) * 512 + (col >> 1)] = lo;
            } else {
                if (col < VOCAB) {
                    out[(size_t)row0 * ldc + col] = v0 + bias[col];
                    out[(size_t)(row0 + 8) * ldc + col] = v2 + bias[col];
                }
                if (col + 1 < VOCAB) {
                    out[(size_t)row0 * ldc + col + 1] = v1 + bias[col + 1];
                    out[(size_t)(row0 + 8) * ldc + col + 1] = v3 + bias[col + 1];
                }
            }
        }
    }
}

// ---------------- launch ----------------
extern "C" void kernel_launch(void* const* d_in, const int* in_sizes, int n_in,
                              void* d_out, int out_size) {
    const int*   x  = (const int*)d_in[0];
    const float* E  = (const float*)d_in[1];
    const float* pe = (const float*)d_in[2];
    const float* Wq = (const float*)d_in[3];
    const float* bq = (const float*)d_in[4];
    const float* Wk = (const float*)d_in[5];
    const float* bk = (const float*)d_in[6];
    const float* Wv = (const float*)d_in[7];
    const float* bv = (const float*)d_in[8];
    const float* Wo = (const float*)d_in[9];
    const float* bo = (const float*)d_in[10];
    const float* Wu = (const float*)d_in[11];
    const float* bu = (const float*)d_in[12];
    float* out = (float*)d_out;

    float *embP, *qkvP, *b3P;
    uint32_t *embA, *catA, *yA, *w3A, *woA, *wuA;
    cudaGetSymbolAddress((void**)&embP, g_emb);
    cudaGetSymbolAddress((void**)&qkvP, g_QKV);
    cudaGetSymbolAddress((void**)&b3P,  g_b3);
    cudaGetSymbolAddress((void**)&embA, g_embA);
    cudaGetSymbolAddress((void**)&catA, g_catA);
    cudaGetSymbolAddress((void**)&yA,   g_yA);
    cudaGetSymbolAddress((void**)&w3A,  g_W3A);
    cudaGetSymbolAddress((void**)&woA,  g_WoA);
    cudaGetSymbolAddress((void**)&wuA,  g_WuA);
    const size_t embN = (size_t)ROWS * EMBED / 2;
    const size_t w3N  = (size_t)EMBED * 3 * EMBED / 2;
    const size_t woN  = (size_t)EMBED * EMBED / 2;
    const size_t wuN  = (size_t)EMBED * VPAD / 2;

    cudaFuncSetAttribute(hmma_gemm<0>, cudaFuncAttributeMaxDynamicSharedMemorySize, GEMM_SMEM);
    cudaFuncSetAttribute(hmma_gemm<1>, cudaFuncAttributeMaxDynamicSharedMemorySize, GEMM_SMEM);
    cudaFuncSetAttribute(hmma_gemm<2>, cudaFuncAttributeMaxDynamicSharedMemorySize, GEMM_SMEM);

    // conversions
    embed_kernel<<<ROWS, 256>>>(x, E, pe);
    convW3<<<(EMBED * 1536 + 255) / 256, 256>>>(Wq, bq, Wk, bk, Wv, bv);
    convWo<<<(EMBED * 512 + 255) / 256, 256>>>(Wo);
    convWu<<<(EMBED * (VPAD / 2) + 255) / 256, 256>>>(Wu);

    // QKV: [4096,1024] @ [1024,3072] -> g_QKV fp32
    hmma_gemm<0><<<dim3(ROWS / 128, 3 * EMBED / 128), 256, GEMM_SMEM>>>(
        embA, embA + embN, w3A, w3A + w3N, b3P, nullptr,
        qkvP, nullptr, nullptr, 3 * EMBED, 3 * EMBED);

    // attention -> g_catA (bf16 hi/lo)
    attn_kernel<<<dim3(BATCH, HEADS), 256>>>();

    // O-proj + bias + residual -> g_yA (bf16 hi/lo)
    hmma_gemm<1><<<dim3(ROWS / 128, EMBED / 128), 256, GEMM_SMEM>>>(
        catA, catA + embN, woA, woA + woN, bo, embP,
        nullptr, yA, yA + embN, EMBED, EMBED);

    // unembed: [4096,1024] @ [1024,50304] -> logits fp32 [4096,50257]
    hmma_gemm<2><<<dim3(ROWS / 128, VPAD / 128), 256, GEMM_SMEM>>>(
        yA, yA + embN, wuA, wuA + wuN, bu, nullptr,
        out, nullptr, nullptr, VPAD, VOCAB);
}

// round 15
// speedup vs baseline: 3.2194x; 1.2915x over previous
#include <cuda_runtime.h>
#include <cuda_bf16.h>
#include <math.h>
#include <stdint.h>

// Problem constants
#define BATCH 64
#define SEQ 64
#define EMBED 1024
#define HEADS 16
#define HDIM 64
#define VOCAB 50257
#define VPAD 50304                    // padded to multiple of 128
#define ROWS (BATCH * SEQ)            // 4096

// ---------------- scratch (device globals; no allocation allowed) ----------------
__device__ __align__(128) float    g_emb[(size_t)ROWS * EMBED];        // fp32 residual
__device__ __align__(128) float    g_QKV[(size_t)ROWS * 3 * EMBED];    // fp32 QKV
__device__ __align__(128) uint32_t g_embA[2][(size_t)ROWS * EMBED / 2];  // bf16x2 hi/lo
__device__ __align__(128) uint32_t g_catA[2][(size_t)ROWS * EMBED / 2];
__device__ __align__(128) uint32_t g_yA[2][(size_t)ROWS * EMBED / 2];
__device__ __align__(128) uint32_t g_W3A[2][(size_t)EMBED * 3 * EMBED / 2];
__device__ __align__(128) uint32_t g_WoA[2][(size_t)EMBED * EMBED / 2];
__device__ __align__(128) uint32_t g_WuA[2][(size_t)EMBED * VPAD / 2];
__device__ __align__(128) float    g_b3[3 * EMBED];

// ============================================================================
// helpers
// ============================================================================
__device__ __forceinline__ uint32_t smem_u32(const void* p) {
    uint32_t a;
    asm("{ .reg .u64 t; cvta.to.shared.u64 t, %1; cvt.u32.u64 %0, t; }" : "=r"(a) : "l"(p));
    return a;
}
__device__ __forceinline__ uint32_t cvt_bf16x2(float lo, float hi) {
    uint32_t r;
    asm("cvt.rn.bf16x2.f32 %0, %1, %2;" : "=r"(r) : "f"(hi), "f"(lo));
    return r;
}
__device__ __forceinline__ void split2(float v0, float v1, uint32_t& hi, uint32_t& lo) {
    hi = cvt_bf16x2(v0, v1);
    float r0 = v0 - __uint_as_float(hi << 16);
    float r1 = v1 - __uint_as_float(hi & 0xFFFF0000u);
    lo = cvt_bf16x2(r0, r1);
}
__device__ __forceinline__ void cp16(uint32_t dst, const void* src) {
    asm volatile("cp.async.cg.shared.global [%0], [%1], 16;" :: "r"(dst), "l"(src));
}
__device__ __forceinline__ void ldsm_x4(uint32_t* r, uint32_t addr) {
    asm volatile("ldmatrix.sync.aligned.m8n8.x4.shared.b16 {%0,%1,%2,%3}, [%4];"
                 : "=r"(r[0]), "=r"(r[1]), "=r"(r[2]), "=r"(r[3]) : "r"(addr));
}
__device__ __forceinline__ void ldsm_x4_t(uint32_t* r, uint32_t addr) {
    asm volatile("ldmatrix.sync.aligned.m8n8.x4.trans.shared.b16 {%0,%1,%2,%3}, [%4];"
                 : "=r"(r[0]), "=r"(r[1]), "=r"(r[2]), "=r"(r[3]) : "r"(addr));
}
__device__ __forceinline__ void mma16816(float* c, const uint32_t* a, const uint32_t* b) {
    asm volatile(
        "mma.sync.aligned.m16n8k16.row.col.f32.bf16.bf16.f32 "
        "{%0,%1,%2,%3}, {%4,%5,%6,%7}, {%8,%9}, {%0,%1,%2,%3};"
        : "+f"(c[0]), "+f"(c[1]), "+f"(c[2]), "+f"(c[3])
        : "r"(a[0]), "r"(a[1]), "r"(a[2]), "r"(a[3]), "r"(b[0]), "r"(b[1]));
}

// ---------------- K1: embedding gather + pe; write fp32 + bf16 hi/lo ----------------
__global__ void embed_kernel(const int* __restrict__ x,
                             const float* __restrict__ E,
                             const float* __restrict__ pe) {
    int row = blockIdx.x;
    int s = row & (SEQ - 1);
    int tok = x[row];
    int i = threadIdx.x;                 // 256 threads * 4 floats
    float4 a = ((const float4*)(E + (size_t)tok * EMBED))[i];
    float4 p = ((const float4*)(pe + (size_t)s * EMBED))[i];
    float4 v = make_float4(a.x + p.x, a.y + p.y, a.z + p.z, a.w + p.w);
    ((float4*)(g_emb + (size_t)row * EMBED))[i] = v;
    uint32_t h0, l0, h1, l1;
    split2(v.x, v.y, h0, l0);
    split2(v.z, v.w, h1, l1);
    size_t idx = (size_t)row * 512 + (size_t)i * 2;
    g_embA[0][idx] = h0; g_embA[0][idx + 1] = h1;
    g_embA[1][idx] = l0; g_embA[1][idx + 1] = l1;
}

// ---------------- conv kernels: repack + bf16 split weights ----------------
__global__ void convW3(const float* __restrict__ Wq, const float* __restrict__ bq,
                       const float* __restrict__ Wk, const float* __restrict__ bk,
                       const float* __restrict__ Wv, const float* __restrict__ bv) {
    int idx = blockIdx.x * 256 + threadIdx.x;       // over 1024*1536 pairs
    if (idx < EMBED * 1536) {
        int d = idx / 1536, p = idx % 1536;
        int col = p * 2;
        int w = col >> 10, rem = col & 1023;
        int h = rem >> 6, e = rem & 63;
        const float* W = (w == 0 ? Wq : (w == 1 ? Wk : Wv));
        size_t sidx = ((size_t)h * EMBED + d) * 64 + e;
        uint32_t hi, lo;
        split2(W[sidx], W[sidx + 1], hi, lo);
        g_W3A[0][(size_t)d * 1536 + p] = hi;
        g_W3A[1][(size_t)d * 1536 + p] = lo;
    }
    if (idx < 3 * EMBED) {
        int w = idx >> 10, rem = idx & 1023;
        const float* B = (w == 0 ? bq : (w == 1 ? bk : bv));
        g_b3[idx] = B[rem];
    }
}

__global__ void convWo(const float* __restrict__ Wo) {
    int idx = blockIdx.x * 256 + threadIdx.x;       // over 1024*512 pairs
    if (idx >= EMBED * 512) return;
    size_t s = (size_t)idx * 2;
    uint32_t hi, lo;
    split2(Wo[s], Wo[s + 1], hi, lo);
    g_WoA[0][idx] = hi;
    g_WoA[1][idx] = lo;
}

__global__ void convWu(const float* __restrict__ Wu) {
    int idx = blockIdx.x * 256 + threadIdx.x;       // over 1024*(VPAD/2)
    if (idx >= EMBED * (VPAD / 2)) return;
    int k = idx / (VPAD / 2), p = idx % (VPAD / 2);
    int n = p * 2;
    float v0 = (n < VOCAB) ? Wu[(size_t)k * VOCAB + n] : 0.f;
    float v1 = (n + 1 < VOCAB) ? Wu[(size_t)k * VOCAB + n + 1] : 0.f;
    uint32_t hi, lo;
    split2(v0, v1, hi, lo);
    g_WuA[0][(size_t)k * (VPAD / 2) + p] = hi;
    g_WuA[1][(size_t)k * (VPAD / 2) + p] = lo;
}

// ---------------- K3: causal attention per (b, h) ----------------
__global__ __launch_bounds__(256) void attn_kernel() {
    int b = blockIdx.x, h = blockIdx.y;
    const float* base = g_QKV + (size_t)b * SEQ * 3072;

    __shared__ float sKV[64][65];
    __shared__ float sS[64][68];

    int tid = threadIdx.x;
    for (int idx = tid; idx < 64 * 64; idx += 256) {
        int r = idx >> 6, c = idx & 63;
        sKV[r][c] = base[(size_t)r * 3072 + 1024 + h * 64 + c];
    }
    __syncthreads();

    int i = tid >> 2;
    int jb = (tid & 3) * 16;
    {
        float accS[16] = {};
        const float4* Q4 = (const float4*)(base + (size_t)i * 3072 + h * 64);
#pragma unroll
        for (int ec = 0; ec < 16; ec++) {
            float4 q = Q4[ec];
#pragma unroll
            for (int jj = 0; jj < 16; jj++) {
                const float* kr = &sKV[jb + jj][ec * 4];
                accS[jj] += q.x * kr[0] + q.y * kr[1] + q.z * kr[2] + q.w * kr[3];
            }
        }
#pragma unroll
        for (int jj = 0; jj < 16; jj++) sS[i][jb + jj] = accS[jj];
    }
    __syncthreads();

    if (tid < 64) {
        int r = tid;
        const float scale = 0.125f;
        float mx = -1e30f;
        for (int j = 0; j <= r; j++) {
            float v = sS[r][j] * scale;
            sS[r][j] = v;
            mx = fmaxf(mx, v);
        }
        float sum = 0.f;
        for (int j = 0; j <= r; j++) {
            float e = expf(sS[r][j] - mx);
            sS[r][j] = e;
            sum += e;
        }
        float inv = 1.f / sum;
        for (int j = 0; j <= r; j++) sS[r][j] *= inv;
        for (int j = r + 1; j < 64; j++) sS[r][j] = 0.f;
    }
    __syncthreads();

    for (int idx = tid; idx < 64 * 64; idx += 256) {
        int r = idx >> 6, c = idx & 63;
        sKV[r][c] = base[(size_t)r * 3072 + 2048 + h * 64 + c];
    }
    __syncthreads();

    int eb = (tid & 3) * 16;
    float accO[16] = {};
    for (int j = 0; j < 64; j++) {
        float w = sS[i][j];
        const float* vr = &sKV[j][eb];
#pragma unroll
        for (int ee = 0; ee < 16; ee++) accO[ee] += w * vr[ee];
    }
    uint32_t hp[8], lp[8];
#pragma unroll
    for (int p = 0; p < 8; p++) split2(accO[2 * p], accO[2 * p + 1], hp[p], lp[p]);
    size_t o = ((size_t)(b * SEQ + i) * 1024 + h * 64 + eb) >> 1;    // mult of 8
    ((uint4*)&g_catA[0][o])[0] = make_uint4(hp[0], hp[1], hp[2], hp[3]);
    ((uint4*)&g_catA[0][o])[1] = make_uint4(hp[4], hp[5], hp[6], hp[7]);
    ((uint4*)&g_catA[1][o])[0] = make_uint4(lp[0], lp[1], lp[2], lp[3]);
    ((uint4*)&g_catA[1][o])[1] = make_uint4(lp[4], lp[5], lp[6], lp[7]);
}

// ============================================================================
// HMMA GEMM: C[M,N] = A[M,1024] @ B[1024,N], 3x bf16 split, fp32 accum.
// CTA tile 128x128, 8 warps (2m x 4n), warp tile 64x32, mma m16n8k16.
// k32 stages, NST=3 cp.async pipeline, ONE __syncthreads per iter, 2 CTAs/SM.
// A smem pitch 80B (20 words = 4 mod 32 -> conflict-free ldsm); B XOR-swizzled.
// MODE 0: out fp32 = C + bias                      (QKV)
// MODE 1: split2(C + bias + resid) -> outHi/outLo  (O-proj -> y bf16 hi/lo)
// MODE 2: out fp32 = C + bias, col < VOCAB guard   (unembed)
// ============================================================================
#define NST 3
#define OFF_AHI 0
#define OFF_ALO 10240
#define OFF_BHI 20480
#define OFF_BLO 28672
#define STG_BYTES 36864
#define GEMM_SMEM (NST * STG_BYTES)     // 110592
#define NITER 32                        // K=1024 / 32

template <int MODE>
__global__ __launch_bounds__(256, 2) void hmma_gemm(
    const uint32_t* __restrict__ Ahi, const uint32_t* __restrict__ Alo,
    const uint32_t* __restrict__ Bhi, const uint32_t* __restrict__ Blo,
    const float* __restrict__ bias, const float* __restrict__ resid,
    float* __restrict__ out, uint32_t* __restrict__ outHi, uint32_t* __restrict__ outLo,
    int ldb, int ldc) {
    extern __shared__ char sm[];
    const uint32_t smb = smem_u32(sm);
    const int t = threadIdx.x;
    const int mBase = blockIdx.x * 128;
    const int nBase = blockIdx.y * 128;

    // ---- global load mapping (cp.async, 8x 16B per thread per k32 stage) ----
    const int aRow = t >> 1, aCh = t & 1;          // A: 128 rows x 4 chunks (2 per thread)
    const int bRow = t >> 3, bCh = t & 7;          // B: 32 rows x 16 chunks (2 per thread)
    const char* aHiP = (const char*)Ahi + (size_t)(mBase + aRow) * 2048;
    const char* aLoP = (const char*)Alo + (size_t)(mBase + aRow) * 2048;
    const char* bHiP = (const char*)Bhi + ((size_t)bRow * ldb + nBase) * 2;
    const char* bLoP = (const char*)Blo + ((size_t)bRow * ldb + nBase) * 2;
    const size_t bStep = (size_t)ldb * 64;         // 32 k-rows * ldb * 2B
    const uint32_t aD0 = aRow * 80 + aCh * 16;     // + 32 for second chunk
    const uint32_t bD0 = bRow * 256 + ((bCh ^ (bRow & 7)) * 16);
    const uint32_t bD1 = bRow * 256 + (((bCh + 8) ^ (bRow & 7)) * 16);

    // ---- compute mapping ----
    const int w = t >> 5, L = t & 31;
    const int wm = w >> 2, wn = w & 3;             // warp tile: (wm*64, wn*32)
    const int mat = L >> 3, r = L & 7;
    const uint32_t aLd = (uint32_t)((wm * 64 + (mat & 1) * 8 + r) * 80 + (mat >> 1) * 16);
    const int kq = (mat & 1) * 8 + r;
    const int qr = L >> 2, qc = (L & 3) * 2;

    float acc[4][4][4] = {};

#define LOAD_TILE(kt) do {                                                     \
        uint32_t _b = smb + ((kt) % NST) * STG_BYTES;                          \
        size_t _ak = (size_t)(kt) * 64;                                        \
        cp16(_b + OFF_AHI + aD0,      aHiP + _ak + aCh * 16);                  \
        cp16(_b + OFF_AHI + aD0 + 32, aHiP + _ak + aCh * 16 + 32);             \
        cp16(_b + OFF_ALO + aD0,      aLoP + _ak + aCh * 16);                  \
        cp16(_b + OFF_ALO + aD0 + 32, aLoP + _ak + aCh * 16 + 32);             \
        size_t _bk = (size_t)(kt) * bStep;                                     \
        cp16(_b + OFF_BHI + bD0, bHiP + _bk + bCh * 16);                       \
        cp16(_b + OFF_BHI + bD1, bHiP + _bk + (bCh + 8) * 16);                 \
        cp16(_b + OFF_BLO + bD0, bLoP + _bk + bCh * 16);                       \
        cp16(_b + OFF_BLO + bD1, bLoP + _bk + (bCh + 8) * 16);                 \
    } while (0)

    LOAD_TILE(0);
    asm volatile("cp.async.commit_group;" ::: "memory");
    LOAD_TILE(1);
    asm volatile("cp.async.commit_group;" ::: "memory");

    for (int kt = 0; kt < NITER; kt++) {
        asm volatile("cp.async.wait_group %0;" :: "n"(1));
        __syncthreads();
        if (kt + 2 < NITER) LOAD_TILE(kt + 2);
        asm volatile("cp.async.commit_group;" ::: "memory");

        const uint32_t sb = smb + (kt % NST) * STG_BYTES;
#pragma unroll
        for (int ks = 0; ks < 2; ks++) {
            uint32_t a[4][4], bh[4][2], bl[4][2];
            const uint32_t aOff = aLd + ks * 32;
#pragma unroll
            for (int i = 0; i < 4; i++) ldsm_x4(a[i], sb + OFF_AHI + aOff + i * 1280);
            const int rr = ks * 16 + kq;
#pragma unroll
            for (int j2 = 0; j2 < 2; j2++) {
                int c = wn * 4 + j2 * 2 + (mat >> 1);
                uint32_t ad = (uint32_t)(rr * 256 + ((c ^ (rr & 7)) * 16));
                uint32_t tmp[4];
                ldsm_x4_t(tmp, sb + OFF_BHI + ad);
                bh[j2 * 2][0] = tmp[0]; bh[j2 * 2][1] = tmp[1];
                bh[j2 * 2 + 1][0] = tmp[2]; bh[j2 * 2 + 1][1] = tmp[3];
                ldsm_x4_t(tmp, sb + OFF_BLO + ad);
                bl[j2 * 2][0] = tmp[0]; bl[j2 * 2][1] = tmp[1];
                bl[j2 * 2 + 1][0] = tmp[2]; bl[j2 * 2 + 1][1] = tmp[3];
            }
            // pass 1: A_hi * (B_hi, B_lo)
#pragma unroll
            for (int i = 0; i < 4; i++)
#pragma unroll
                for (int j = 0; j < 4; j++) {
                    mma16816(acc[i][j], a[i], bh[j]);
                    mma16816(acc[i][j], a[i], bl[j]);
                }
            // pass 2: reload A_lo into same regs, * B_hi
#pragma unroll
            for (int i = 0; i < 4; i++) ldsm_x4(a[i], sb + OFF_ALO + aOff + i * 1280);
#pragma unroll
            for (int i = 0; i < 4; i++)
#pragma unroll
                for (int j = 0; j < 4; j++)
                    mma16816(acc[i][j], a[i], bh[j]);
        }
    }

    // ---- epilogue ----
#pragma unroll
    for (int i = 0; i < 4; i++) {
        const int row0 = mBase + wm * 64 + i * 16 + qr;
#pragma unroll
        for (int j = 0; j < 4; j++) {
            const int col = nBase + wn * 32 + j * 8 + qc;
            float v0 = acc[i][j][0], v1 = acc[i][j][1];
            float v2 = acc[i][j][2], v3 = acc[i][j][3];
            if (MODE == 0) {
                float b0 = bias[col], b1 = bias[col + 1];
                *(float2*)&out[(size_t)row0 * ldc + col] = make_float2(v0 + b0, v1 + b1);
                *(float2*)&out[(size_t)(row0 + 8) * ldc + col] = make_float2(v2 + b0, v3 + b1);
            } else if (MODE == 1) {
                float b0 = bias[col], b1 = bias[col + 1];
                float u0 = v0 + b0 + resid[(size_t)row0 * 1024 + col];
                float u1 = v1 + b1 + resid[(size_t)row0 * 1024 + col + 1];
                uint32_t hi, lo;
                split2(u0, u1, hi, lo);
                outHi[(size_t)row0 * 512 + (col >> 1)] = hi;
                outLo[(size_t)row0 * 512 + (col >> 1)] = lo;
                float u2 = v2 + b0 + resid[(size_t)(row0 + 8) * 1024 + col];
                float u3 = v3 + b1 + resid[(size_t)(row0 + 8) * 1024 + col + 1];
                split2(u2, u3, hi, lo);
                outHi[(size_t)(row0 + 8) * 512 + (col >> 1)] = hi;
                outLo[(size_t)(row0 + 8) * 512 + (col >> 1)] = lo;
            } else {
                if (col < VOCAB) {
                    out[(size_t)row0 * ldc + col] = v0 + bias[col];
                    out[(size_t)(row0 + 8) * ldc + col] = v2 + bias[col];
                }
                if (col + 1 < VOCAB) {
                    out[(size_t)row0 * ldc + col + 1] = v1 + bias[col + 1];
                    out[(size_t)(row0 + 8) * ldc + col + 1] = v3 + bias[col + 1];
                }
            }
        }
    }
}

// ---------------- launch ----------------
extern "C" void kernel_launch(void* const* d_in, const int* in_sizes, int n_in,
                              void* d_out, int out_size) {
    const int*   x  = (const int*)d_in[0];
    const float* E  = (const float*)d_in[1];
    const float* pe = (const float*)d_in[2];
    const float* Wq = (const float*)d_in[3];
    const float* bq = (const float*)d_in[4];
    const float* Wk = (const float*)d_in[5];
    const float* bk = (const float*)d_in[6];
    const float* Wv = (const float*)d_in[7];
    const float* bv = (const float*)d_in[8];
    const float* Wo = (const float*)d_in[9];
    const float* bo = (const float*)d_in[10];
    const float* Wu = (const float*)d_in[11];
    const float* bu = (const float*)d_in[12];
    float* out = (float*)d_out;

    float *embP, *qkvP, *b3P;
    uint32_t *embA, *catA, *yA, *w3A, *woA, *wuA;
    cudaGetSymbolAddress((void**)&embP, g_emb);
    cudaGetSymbolAddress((void**)&qkvP, g_QKV);
    cudaGetSymbolAddress((void**)&b3P,  g_b3);
    cudaGetSymbolAddress((void**)&embA, g_embA);
    cudaGetSymbolAddress((void**)&catA, g_catA);
    cudaGetSymbolAddress((void**)&yA,   g_yA);
    cudaGetSymbolAddress((void**)&w3A,  g_W3A);
    cudaGetSymbolAddress((void**)&woA,  g_WoA);
    cudaGetSymbolAddress((void**)&wuA,  g_WuA);
    const size_t embN = (size_t)ROWS * EMBED / 2;
    const size_t w3N  = (size_t)EMBED * 3 * EMBED / 2;
    const size_t woN  = (size_t)EMBED * EMBED / 2;
    const size_t wuN  = (size_t)EMBED * VPAD / 2;

    cudaFuncSetAttribute(hmma_gemm<0>, cudaFuncAttributeMaxDynamicSharedMemorySize, GEMM_SMEM);
    cudaFuncSetAttribute(hmma_gemm<1>, cudaFuncAttributeMaxDynamicSharedMemorySize, GEMM_SMEM);
    cudaFuncSetAttribute(hmma_gemm<2>, cudaFuncAttributeMaxDynamicSharedMemorySize, GEMM_SMEM);

    // conversions
    embed_kernel<<<ROWS, 256>>>(x, E, pe);
    convW3<<<(EMBED * 1536 + 255) / 256, 256>>>(Wq, bq, Wk, bk, Wv, bv);
    convWo<<<(EMBED * 512 + 255) / 256, 256>>>(Wo);
    convWu<<<(EMBED * (VPAD / 2) + 255) / 256, 256>>>(Wu);

    // QKV: [4096,1024] @ [1024,3072] -> g_QKV fp32
    hmma_gemm<0><<<dim3(ROWS / 128, 3 * EMBED / 128), 256, GEMM_SMEM>>>(
        embA, embA + embN, w3A, w3A + w3N, b3P, nullptr,
        qkvP, nullptr, nullptr, 3 * EMBED, 3 * EMBED);

    // attention -> g_catA (bf16 hi/lo)
    attn_kernel<<<dim3(BATCH, HEADS), 256>>>();

    // O-proj + bias + residual -> g_yA (bf16 hi/lo)
    hmma_gemm<1><<<dim3(ROWS / 128, EMBED / 128), 256, GEMM_SMEM>>>(
        catA, catA + embN, woA, woA + woN, bo, embP,
        nullptr, yA, yA + embN, EMBED, EMBED);

    // unembed: [4096,1024] @ [1024,50304] -> logits fp32 [4096,50257]
    hmma_gemm<2><<<dim3(ROWS / 128, VPAD / 128), 256, GEMM_SMEM>>>(
        yA, yA + embN, wuA, wuA + wuN, bu, nullptr,
        out, nullptr, nullptr, VPAD, VOCAB);
}